// round 10
// baseline (speedup 1.0000x reference)
#include <cuda_runtime.h>

#define NB_NODES 4096
#define NB_EMAX  2048
#define NB_L     8
#define NB_HID   128
#define NB_TH    512
#define NB_SMAX  256    // max edges per graph (E/G = 16 expected)

// ---------------------------------------------------------------------------
// Template-recursive walk expansion: edge `cur` sits at depth K-1; iterate its
// successors p (depth K): rule dst_p == src_cur && src_p != dst_cur.
// If p == start, a closed non-backtracking walk of length K closes -> cnt[K-1]
// (= diag(B^K)). Fully inlined: all per-depth state lives in registers.
// ---------------------------------------------------------------------------
template<int K>
__device__ __forceinline__ void walk(const int* __restrict__ se,
                                     const short* __restrict__ sn,
                                     const int* __restrict__ sh,
                                     int cur, int start, int* cnt) {
    if constexpr (K <= NB_L) {
        const int e      = se[cur];
        const int node   = e & 0xFFFF;   // src_cur
        const int curdst = e >> 16;      // dst_cur
        for (int p = sh[node]; p >= 0; p = sn[p]) {
            if ((se[p] & 0xFFFF) == curdst) continue;   // backtracking
            if (p == start) cnt[K - 1]++;
            walk<K + 1>(se, sn, sh, p, start, cnt);
        }
    }
}

// ---------------------------------------------------------------------------
// One block per graph; fully independent blocks.
// ---------------------------------------------------------------------------
__global__ __launch_bounds__(NB_TH, 1)
void k_graph(const int* __restrict__ ei, const int* __restrict__ eg,
             const float* __restrict__ W1, const float* __restrict__ b1,
             const float* __restrict__ W2, const float* __restrict__ b2,
             float* __restrict__ out, int E) {
    __shared__ int   s_head[NB_NODES];     // 16 KB (int: shared atomicExch target)
    __shared__ int   s_edge[NB_EMAX];      //  8 KB  src | dst<<16
    __shared__ short s_next[NB_EMAX];      //  4 KB
    __shared__ short s_starts[NB_SMAX];
    __shared__ int   s_ns;
    __shared__ int   s_sigv[NB_L];         // integer closed-walk counts
    __shared__ float s_part[4];

    const int g    = blockIdx.x;
    const int tid  = threadIdx.x;
    const int lane = tid & 31;
    const int warp = tid >> 5;

    // ---- 1: preload MLP weights (threads 0..127); hidden under build ----
    float w[NB_L], b1v = 0.0f, w2v = 0.0f;
    if (tid < NB_HID) {
#pragma unroll
        for (int l = 0; l < NB_L; l++) w[l] = __ldg(&W1[l * NB_HID + tid]);
        b1v = __ldg(&b1[tid]);
        w2v = __ldg(&W2[tid]);
    }

    // ---- 2: init head (vectorized) / counters ----
    {
        int4* h4 = (int4*)s_head;
        const int m1 = -1;
        const int4 mv = make_int4(m1, m1, m1, m1);
#pragma unroll
        for (int v = tid; v < NB_NODES / 4; v += NB_TH) h4[v] = mv;
    }
    if (tid < NB_L) s_sigv[tid] = 0;
    if (tid == 0)  s_ns = 0;
    __syncthreads();

    // ---- 3: fused stage + adjacency build + start collection ----
    // ei flat = [src[0..E), dst[0..E)]; vectorized int4 loads.
    {
        const int4* ei4 = (const int4*)ei;
        const int4* eg4 = (const int4*)eg;
        const int nq = E >> 2;                       // E = 2048 -> 512
        for (int t = tid; t < nq; t += NB_TH) {
            const int4 s4 = ei4[t];
            const int4 d4 = ei4[nq + t];
            const int4 g4 = eg4[t];
            const int j = t << 2;
            s_edge[j + 0] = (s4.x & 0xFFFF) | (d4.x << 16);
            s_edge[j + 1] = (s4.y & 0xFFFF) | (d4.y << 16);
            s_edge[j + 2] = (s4.z & 0xFFFF) | (d4.z << 16);
            s_edge[j + 3] = (s4.w & 0xFFFF) | (d4.w << 16);
            s_next[j + 0] = (short)atomicExch(&s_head[d4.x], j + 0);
            s_next[j + 1] = (short)atomicExch(&s_head[d4.y], j + 1);
            s_next[j + 2] = (short)atomicExch(&s_head[d4.z], j + 2);
            s_next[j + 3] = (short)atomicExch(&s_head[d4.w], j + 3);
            if (g4.x == g) { int p = atomicAdd(&s_ns, 1); if (p < NB_SMAX) s_starts[p] = (short)(j + 0); }
            if (g4.y == g) { int p = atomicAdd(&s_ns, 1); if (p < NB_SMAX) s_starts[p] = (short)(j + 1); }
            if (g4.z == g) { int p = atomicAdd(&s_ns, 1); if (p < NB_SMAX) s_starts[p] = (short)(j + 2); }
            if (g4.w == g) { int p = atomicAdd(&s_ns, 1); if (p < NB_SMAX) s_starts[p] = (short)(j + 3); }
        }
    }
    __syncthreads();

    // ---- 4: warp-per-start DFS, lane-strided over DEPTH-2 (p,q) pairs ----
    // All lanes co-iterate succ(start) and succ(p) keeping a consistent item
    // counter; each (p,q) pair is owned by one lane, which checks the
    // length-2 closure and expands the subtree below q. This splits hot
    // subtrees at two levels (tail ~ b1*b2 / 32 instead of b1 / 32).
    // length-1 closure is structurally impossible (self-loop && non-self-loop).
    int cnt[NB_L];
#pragma unroll
    for (int k = 0; k < NB_L; k++) cnt[k] = 0;

    const int ns = min(s_ns, NB_SMAX);
    for (int si = warp; si < ns; si += NB_TH >> 5) {
        const int i    = s_starts[si];
        const int e0   = s_edge[i];
        const int isrc = e0 & 0xFFFF;
        const int idst = e0 >> 16;
        int idx = 0;
        for (int p = s_head[isrc]; p >= 0; p = s_next[p]) {
            const int ep   = s_edge[p];
            const int psrc = ep & 0xFFFF;
            if (psrc == idst) continue;               // backtracking at depth 1
            const int pdst = ep >> 16;                // == isrc
            for (int q = s_head[psrc]; q >= 0; q = s_next[q]) {
                if ((s_edge[q] & 0xFFFF) == pdst) continue;   // backtracking
                if ((idx++ & 31) != lane) continue;   // one owner lane per pair
                if (q == i) cnt[1]++;                 // closed walk, length 2
                walk<3>(s_edge, s_next, s_head, q, i, cnt);   // q at depth 2
            }
        }
    }
#pragma unroll
    for (int k = 1; k < NB_L; k++) {
        int v = cnt[k];
#pragma unroll
        for (int o = 16; o; o >>= 1) v += __shfl_xor_sync(0xffffffffu, v, o);
        if (lane == 0 && v) atomicAdd(&s_sigv[k], v);
    }
    __syncthreads();

    // ---- 5: MLP for this graph ----
    float v = 0.0f;
    if (tid < NB_HID) {
        float h = b1v;
#pragma unroll
        for (int l = 0; l < NB_L; l++)
            h = fmaf((float)s_sigv[l], w[l], h);
        v = fmaxf(h, 0.0f) * w2v;
    }
#pragma unroll
    for (int o = 16; o; o >>= 1) v += __shfl_xor_sync(0xffffffffu, v, o);
    if (tid < NB_HID && lane == 0) s_part[warp] = v;
    __syncthreads();
    if (tid == 0) {
        float tot = __ldg(&b2[0]);
#pragma unroll
        for (int ww = 0; ww < NB_HID / 32; ww++) tot += s_part[ww];
        out[g] = tot;
    }
}

extern "C" void kernel_launch(void* const* d_in, const int* in_sizes, int n_in,
                              void* d_out, int out_size) {
    const int*   ei = (const int*)  d_in[0];   // edge_index [2, E]
    const int*   eg = (const int*)  d_in[1];   // edge_graph [E]
    const float* W1 = (const float*)d_in[2];   // [L, HID]
    const float* b1 = (const float*)d_in[3];   // [HID]
    const float* W2 = (const float*)d_in[4];   // [HID, 1]
    const float* b2 = (const float*)d_in[5];   // [1]
    float* out = (float*)d_out;                // [G, 1]

    const int E = in_sizes[0] / 2;
    const int G = out_size;

    k_graph<<<G, NB_TH>>>(ei, eg, W1, b1, W2, b2, out, E);
}

// round 11
// speedup vs baseline: 1.0607x; 1.0607x over previous
#include <cuda_runtime.h>

#define NB_NODES 4096
#define NB_EMAX  2048
#define NB_L     8
#define NB_HID   128
#define NB_TH    512
#define NB_SMAX  256    // max edges per graph (E/G = 16 expected)

// ---------------------------------------------------------------------------
// Template-recursive walk expansion: edge `cur` sits at depth K-1; iterate its
// successors p (depth K): rule dst_p == src_cur && src_p != dst_cur.
// If p == start, a closed non-backtracking walk of length K closes -> cnt[K-1]
// (= diag(B^K)). Fully inlined: all per-depth state lives in registers.
// ---------------------------------------------------------------------------
template<int K>
__device__ __forceinline__ void walk(const int* __restrict__ se,
                                     const short* __restrict__ sn,
                                     const int* __restrict__ sh,
                                     int cur, int start, int* cnt) {
    if constexpr (K <= NB_L) {
        const int e      = se[cur];
        const int node   = e & 0xFFFF;   // src_cur
        const int curdst = e >> 16;      // dst_cur
        for (int p = sh[node]; p >= 0; p = sn[p]) {
            if ((se[p] & 0xFFFF) == curdst) continue;   // backtracking
            if (p == start) cnt[K - 1]++;
            walk<K + 1>(se, sn, sh, p, start, cnt);
        }
    }
}

// ---------------------------------------------------------------------------
// One block per graph; fully independent blocks.
// ---------------------------------------------------------------------------
__global__ __launch_bounds__(NB_TH, 1)
void k_graph(const int* __restrict__ ei, const int* __restrict__ eg,
             const float* __restrict__ W1, const float* __restrict__ b1,
             const float* __restrict__ W2, const float* __restrict__ b2,
             float* __restrict__ out, int E) {
    __shared__ int   s_head[NB_NODES];     // 16 KB (int: shared atomicExch target)
    __shared__ int   s_edge[NB_EMAX];      //  8 KB  src | dst<<16
    __shared__ short s_next[NB_EMAX];      //  4 KB
    __shared__ short s_starts[NB_SMAX];
    __shared__ int   s_ns;
    __shared__ int   s_sigv[NB_L];         // integer closed-walk counts
    __shared__ float s_part[4];

    const int g    = blockIdx.x;
    const int tid  = threadIdx.x;
    const int lane = tid & 31;
    const int warp = tid >> 5;

    // ---- 0: PREFETCH everything global into registers at kernel entry ----
    // Staging loads issue before the init loop + barrier so their memory
    // latency overlaps that work instead of sitting on the critical path.
    const int4* ei4 = (const int4*)ei;
    const int4* eg4 = (const int4*)eg;
    const int nq = E >> 2;                 // E = 2048 -> 512 (== NB_TH)
    int4 s4, d4, g4;
    const int t0 = tid;
    const bool have0 = (t0 < nq);
    if (have0) {
        s4 = ei4[t0];
        d4 = ei4[nq + t0];
        g4 = eg4[t0];
    }
    float w[NB_L], b1v = 0.0f, w2v = 0.0f;
    if (tid < NB_HID) {
#pragma unroll
        for (int l = 0; l < NB_L; l++) w[l] = __ldg(&W1[l * NB_HID + tid]);
        b1v = __ldg(&b1[tid]);
        w2v = __ldg(&W2[tid]);
    }

    // ---- 1: init head (vectorized) / counters (overlaps prefetch latency) --
    {
        int4* h4 = (int4*)s_head;
        const int4 mv = make_int4(-1, -1, -1, -1);
#pragma unroll
        for (int v = tid; v < NB_NODES / 4; v += NB_TH) h4[v] = mv;
    }
    if (tid < NB_L) s_sigv[tid] = 0;
    if (tid == 0)  s_ns = 0;
    __syncthreads();

    // ---- 2: stage + adjacency build + start collection (prefetched regs) ---
    for (int t = t0; t < nq; t += NB_TH) {
        if (t != t0) { s4 = ei4[t]; d4 = ei4[nq + t]; g4 = eg4[t]; }
        const int j = t << 2;
        s_edge[j + 0] = (s4.x & 0xFFFF) | (d4.x << 16);
        s_edge[j + 1] = (s4.y & 0xFFFF) | (d4.y << 16);
        s_edge[j + 2] = (s4.z & 0xFFFF) | (d4.z << 16);
        s_edge[j + 3] = (s4.w & 0xFFFF) | (d4.w << 16);
        s_next[j + 0] = (short)atomicExch(&s_head[d4.x], j + 0);
        s_next[j + 1] = (short)atomicExch(&s_head[d4.y], j + 1);
        s_next[j + 2] = (short)atomicExch(&s_head[d4.z], j + 2);
        s_next[j + 3] = (short)atomicExch(&s_head[d4.w], j + 3);
        if (g4.x == g) { int p = atomicAdd(&s_ns, 1); if (p < NB_SMAX) s_starts[p] = (short)(j + 0); }
        if (g4.y == g) { int p = atomicAdd(&s_ns, 1); if (p < NB_SMAX) s_starts[p] = (short)(j + 1); }
        if (g4.z == g) { int p = atomicAdd(&s_ns, 1); if (p < NB_SMAX) s_starts[p] = (short)(j + 2); }
        if (g4.w == g) { int p = atomicAdd(&s_ns, 1); if (p < NB_SMAX) s_starts[p] = (short)(j + 3); }
    }
    __syncthreads();

    // ---- 3: warp-per-start DFS, lane-strided depth-1 children (R9) --------
    // length-1 closure is structurally impossible (self-loop && non-self-loop).
    int cnt[NB_L];
#pragma unroll
    for (int k = 0; k < NB_L; k++) cnt[k] = 0;

    const int ns = min(s_ns, NB_SMAX);
    for (int si = warp; si < ns; si += NB_TH >> 5) {
        const int i    = s_starts[si];
        const int e0   = s_edge[i];
        const int isrc = e0 & 0xFFFF;
        const int idst = e0 >> 16;
        int idx = 0;
        for (int p = s_head[isrc]; p >= 0; p = s_next[p]) {
            if ((s_edge[p] & 0xFFFF) == idst) continue;  // backtracking, depth 1
            if ((idx++ & 31) != lane) continue;          // stride over lanes
            walk<2>(s_edge, s_next, s_head, p, i, cnt);  // p at depth 1
        }
    }
#pragma unroll
    for (int k = 1; k < NB_L; k++) {
        int v = cnt[k];
#pragma unroll
        for (int o = 16; o; o >>= 1) v += __shfl_xor_sync(0xffffffffu, v, o);
        if (lane == 0 && v) atomicAdd(&s_sigv[k], v);
    }
    __syncthreads();

    // ---- 4: MLP for this graph --------------------------------------------
    float v = 0.0f;
    if (tid < NB_HID) {
        float h = b1v;
#pragma unroll
        for (int l = 0; l < NB_L; l++)
            h = fmaf((float)s_sigv[l], w[l], h);
        v = fmaxf(h, 0.0f) * w2v;
    }
#pragma unroll
    for (int o = 16; o; o >>= 1) v += __shfl_xor_sync(0xffffffffu, v, o);
    if (tid < NB_HID && lane == 0) s_part[warp] = v;
    __syncthreads();
    if (tid == 0) {
        float tot = __ldg(&b2[0]);
#pragma unroll
        for (int ww = 0; ww < NB_HID / 32; ww++) tot += s_part[ww];
        out[g] = tot;
    }
}

extern "C" void kernel_launch(void* const* d_in, const int* in_sizes, int n_in,
                              void* d_out, int out_size) {
    const int*   ei = (const int*)  d_in[0];   // edge_index [2, E]
    const int*   eg = (const int*)  d_in[1];   // edge_graph [E]
    const float* W1 = (const float*)d_in[2];   // [L, HID]
    const float* b1 = (const float*)d_in[3];   // [HID]
    const float* W2 = (const float*)d_in[4];   // [HID, 1]
    const float* b2 = (const float*)d_in[5];   // [1]
    float* out = (float*)d_out;                // [G, 1]

    const int E = in_sizes[0] / 2;
    const int G = out_size;

    k_graph<<<G, NB_TH>>>(ei, eg, W1, b1, W2, b2, out, E);
}

// round 12
// speedup vs baseline: 1.0645x; 1.0036x over previous
#include <cuda_runtime.h>

#define NB_NODES 4096
#define NB_EMAX  2048
#define NB_L     8
#define NB_HID   128
#define NB_TH    512
#define NB_SMAX  256    // max edges per graph (E/G = 16 expected)
#define NB_QCAP  512    // per-depth queue cap (expected ~8-16 items)

// ---------------------------------------------------------------------------
// Template-recursive walk expansion: edge `cur` sits at depth K-1; iterate its
// successors p (depth K): rule dst_p == src_cur && src_p != dst_cur.
// If p == start, a closed non-backtracking walk of length K closes -> cnt[K-1]
// (= diag(B^K)). Fully inlined: all per-depth state lives in registers.
// ---------------------------------------------------------------------------
template<int K>
__device__ __forceinline__ void walk(const int* __restrict__ se,
                                     const short* __restrict__ sn,
                                     const int* __restrict__ sh,
                                     int cur, int start, int* cnt) {
    if constexpr (K <= NB_L) {
        const int e      = se[cur];
        const int node   = e & 0xFFFF;   // src_cur
        const int curdst = e >> 16;      // dst_cur
        for (int p = sh[node]; p >= 0; p = sn[p]) {
            if ((se[p] & 0xFFFF) == curdst) continue;   // backtracking
            if (p == start) cnt[K - 1]++;
            walk<K + 1>(se, sn, sh, p, start, cnt);
        }
    }
}

// ---------------------------------------------------------------------------
// One block per graph; fully independent blocks.
// ---------------------------------------------------------------------------
__global__ __launch_bounds__(NB_TH, 1)
void k_graph(const int* __restrict__ ei, const int* __restrict__ eg,
             const float* __restrict__ W1, const float* __restrict__ b1,
             const float* __restrict__ W2, const float* __restrict__ b2,
             float* __restrict__ out, int E) {
    __shared__ int   s_head[NB_NODES];     // 16 KB (int: shared atomicExch target)
    __shared__ int   s_edge[NB_EMAX];      //  8 KB  src | dst<<16
    __shared__ short s_next[NB_EMAX];      //  4 KB
    __shared__ short s_starts[NB_SMAX];
    __shared__ int   s_q1[NB_QCAP];        //  2 KB  depth-1 items: start<<12 | cur
    __shared__ int   s_q2[NB_QCAP];        //  2 KB  depth-2 items
    __shared__ int   s_q3[NB_QCAP];        //  2 KB  depth-3 items
    __shared__ int   s_ns, s_n1, s_n2, s_n3;
    __shared__ int   s_sigv[NB_L];         // integer closed-walk counts
    __shared__ float s_part[4];

    const int g    = blockIdx.x;
    const int tid  = threadIdx.x;
    const int lane = tid & 31;
    const int warp = tid >> 5;

    // ---- 0: PREFETCH global data into registers at kernel entry ----
    const int4* ei4 = (const int4*)ei;
    const int4* eg4 = (const int4*)eg;
    const int nq = E >> 2;                 // E = 2048 -> 512 (== NB_TH)
    int4 s4, d4, g4;
    const int t0 = tid;
    if (t0 < nq) {
        s4 = ei4[t0];
        d4 = ei4[nq + t0];
        g4 = eg4[t0];
    }
    float w[NB_L], b1v = 0.0f, w2v = 0.0f;
    if (tid < NB_HID) {
#pragma unroll
        for (int l = 0; l < NB_L; l++) w[l] = __ldg(&W1[l * NB_HID + tid]);
        b1v = __ldg(&b1[tid]);
        w2v = __ldg(&W2[tid]);
    }

    // ---- 1: init head (vectorized) / counters (overlaps prefetch latency) --
    {
        int4* h4 = (int4*)s_head;
        const int4 mv = make_int4(-1, -1, -1, -1);
#pragma unroll
        for (int v = tid; v < NB_NODES / 4; v += NB_TH) h4[v] = mv;
    }
    if (tid < NB_L) s_sigv[tid] = 0;
    if (tid == 0) { s_ns = 0; s_n1 = 0; s_n2 = 0; s_n3 = 0; }
    __syncthreads();

    // ---- 2: stage + adjacency build + start collection (prefetched regs) ---
    for (int t = t0; t < nq; t += NB_TH) {
        if (t != t0) { s4 = ei4[t]; d4 = ei4[nq + t]; g4 = eg4[t]; }
        const int j = t << 2;
        s_edge[j + 0] = (s4.x & 0xFFFF) | (d4.x << 16);
        s_edge[j + 1] = (s4.y & 0xFFFF) | (d4.y << 16);
        s_edge[j + 2] = (s4.z & 0xFFFF) | (d4.z << 16);
        s_edge[j + 3] = (s4.w & 0xFFFF) | (d4.w << 16);
        s_next[j + 0] = (short)atomicExch(&s_head[d4.x], j + 0);
        s_next[j + 1] = (short)atomicExch(&s_head[d4.y], j + 1);
        s_next[j + 2] = (short)atomicExch(&s_head[d4.z], j + 2);
        s_next[j + 3] = (short)atomicExch(&s_head[d4.w], j + 3);
        if (g4.x == g) { int p = atomicAdd(&s_ns, 1); if (p < NB_SMAX) s_starts[p] = (short)(j + 0); }
        if (g4.y == g) { int p = atomicAdd(&s_ns, 1); if (p < NB_SMAX) s_starts[p] = (short)(j + 1); }
        if (g4.z == g) { int p = atomicAdd(&s_ns, 1); if (p < NB_SMAX) s_starts[p] = (short)(j + 2); }
        if (g4.w == g) { int p = atomicAdd(&s_ns, 1); if (p < NB_SMAX) s_starts[p] = (short)(j + 3); }
    }
    __syncthreads();

    // ---- 3A: expand starts -> depth-1 items (length-1 closure impossible) --
    const int ns = min(s_ns, NB_SMAX);
    for (int st = tid; st < ns; st += NB_TH) {
        const int i    = s_starts[st];
        const int e0   = s_edge[i];
        const int isrc = e0 & 0xFFFF;
        const int idst = e0 >> 16;
        for (int p = s_head[isrc]; p >= 0; p = s_next[p]) {
            if ((s_edge[p] & 0xFFFF) == idst) continue;
            int pos = atomicAdd(&s_n1, 1);
            if (pos < NB_QCAP) s_q1[pos] = (i << 12) | p;
        }
    }
    __syncthreads();

    // ---- 3B: depth-1 -> depth-2 items; length-2 closures -> sig[1] ---------
    const int n1 = min(s_n1, NB_QCAP);
    for (int it = tid; it < n1; it += NB_TH) {
        const int item = s_q1[it];
        const int i    = item >> 12;
        const int ep   = s_edge[item & 0xFFF];
        const int psrc = ep & 0xFFFF;
        const int pdst = ep >> 16;
        for (int q = s_head[psrc]; q >= 0; q = s_next[q]) {
            if ((s_edge[q] & 0xFFFF) == pdst) continue;
            if (q == i) atomicAdd(&s_sigv[1], 1);
            int pos = atomicAdd(&s_n2, 1);
            if (pos < NB_QCAP) s_q2[pos] = (i << 12) | q;
        }
    }
    __syncthreads();

    // ---- 3C: depth-2 -> depth-3 items; length-3 closures -> sig[2] ---------
    const int n2 = min(s_n2, NB_QCAP);
    for (int it = tid; it < n2; it += NB_TH) {
        const int item = s_q2[it];
        const int i    = item >> 12;
        const int eq   = s_edge[item & 0xFFF];
        const int qsrc = eq & 0xFFFF;
        const int qdst = eq >> 16;
        for (int r = s_head[qsrc]; r >= 0; r = s_next[r]) {
            if ((s_edge[r] & 0xFFFF) == qdst) continue;
            if (r == i) atomicAdd(&s_sigv[2], 1);
            int pos = atomicAdd(&s_n3, 1);
            if (pos < NB_QCAP) s_q3[pos] = (i << 12) | r;
        }
    }
    __syncthreads();

    // ---- 3D: DFS the remaining 5 levels under each depth-3 item ------------
    int cnt[NB_L];
#pragma unroll
    for (int k = 0; k < NB_L; k++) cnt[k] = 0;
    const int n3 = min(s_n3, NB_QCAP);
    for (int it = tid; it < n3; it += NB_TH) {
        const int item = s_q3[it];
        walk<4>(s_edge, s_next, s_head, item & 0xFFF, item >> 12, cnt);
    }
#pragma unroll
    for (int k = 3; k < NB_L; k++)
        if (cnt[k]) atomicAdd(&s_sigv[k], cnt[k]);
    __syncthreads();

    // ---- 4: MLP for this graph --------------------------------------------
    float v = 0.0f;
    if (tid < NB_HID) {
        float h = b1v;
#pragma unroll
        for (int l = 0; l < NB_L; l++)
            h = fmaf((float)s_sigv[l], w[l], h);
        v = fmaxf(h, 0.0f) * w2v;
    }
#pragma unroll
    for (int o = 16; o; o >>= 1) v += __shfl_xor_sync(0xffffffffu, v, o);
    if (tid < NB_HID && lane == 0) s_part[warp] = v;
    __syncthreads();
    if (tid == 0) {
        float tot = __ldg(&b2[0]);
#pragma unroll
        for (int ww = 0; ww < NB_HID / 32; ww++) tot += s_part[ww];
        out[g] = tot;
    }
}

extern "C" void kernel_launch(void* const* d_in, const int* in_sizes, int n_in,
                              void* d_out, int out_size) {
    const int*   ei = (const int*)  d_in[0];   // edge_index [2, E]
    const int*   eg = (const int*)  d_in[1];   // edge_graph [E]
    const float* W1 = (const float*)d_in[2];   // [L, HID]
    const float* b1 = (const float*)d_in[3];   // [HID]
    const float* W2 = (const float*)d_in[4];   // [HID, 1]
    const float* b2 = (const float*)d_in[5];   // [1]
    float* out = (float*)d_out;                // [G, 1]

    const int E = in_sizes[0] / 2;
    const int G = out_size;

    k_graph<<<G, NB_TH>>>(ei, eg, W1, b1, W2, b2, out, E);
}